// round 14
// baseline (speedup 1.0000x reference)
#include <cuda_runtime.h>
#include <cuda_fp16.h>
#include <cstdint>
#include <cstring>

// Problem dims
#define FIN   4096
#define FOUT  4096
#define MTOT  4096   // 2 * 2048

#define KCHUNKS 64          // K chunks of 64
#define NSTAGE  4
#define A_BYTES      16384  // 128 rows x 128B (this CTA's M-half)
#define BH_BYTES     16384  // one B half: 128 rows x 128B
#define B_BYTES      32768
#define STAGE_BYTES  49152  // A + B0half + B1half
#define TX_BYTES     49152  // per-CTA TMA bytes per stage

// Persistent schedule: 128 tiles (256M x 512N) over 74 cg2 pairs.
#define NPAIRS   74
#define NTILES   128
#define TWOTILE  (NTILES - NPAIRS)   // 54 pairs run 2 tiles
#define GEMM_CTAS 148

// prep: chunk-major items; per chunk 32 A-blocks + 16 B-blocks = 48
#define ITEMS_PER_CHUNK 48
#define PREP_ITEMS (KCHUNKS * ITEMS_PER_CHUNK)   // 3072
#define RDY_TARGET 48u

// SMEM layout (dynamic):
//   [0..4)      TMEM base ptr
//   [8..72)     full[s]=8+16s, empty[s]=16+16s  (s=0..3)
//   [72..80)    done mbarrier   (per-tile, parity 0 then 1)
//   [80..88)    epifree mbarrier (count 2, single use)
//   [1024 + s*49152)  stage s: A(16K) | B0half(16K) | B1half(16K)
//   [197632..214528)  epilogue scratch: 4 warps x 4224B
#define SM_BAR     8
#define SM_DONE    72
#define SM_EPIFREE 80
#define SM_TILE0   1024
#define SM_SCRATCH (1024 + NSTAGE * STAGE_BYTES)          // 197632
#define SMEM_BYTES (SM_SCRATCH + 4 * 4224)                // 214528, occ 1

// idesc kind::f16 cg2: dtype=F32(1<<4), a/b=F16(0), N=256 -> 32<<17, M=256 -> 16<<24
#define IDESC_CG2 0x10400010u
#define PEER_MASK 0xFEFFFFFFu

#if defined(__CUDA_ARCH__) && \
    (defined(__CUDA_ARCH_FEAT_SM103_ALL) || defined(__CUDA_ARCH_FEAT_SM100_ALL) || \
     defined(__CUDA_ARCH_FEAT_SM101_ALL))
#define HAS_TCGEN05 1
#else
#define HAS_TCGEN05 0
#endif

// fp16 staging in chunk-blocked, pre-SW128-swizzled layout:
// g_A: [mtile(32 x 128rows)][chunk(64)][16384B]
// g_B: [ntile(16 x 256rows)][chunk(64)][32768B]
__device__ __half g_A[(size_t)MTOT * FIN];
__device__ __half g_B[(size_t)FOUT * FIN];

// per-chunk readiness counters (prep warps -> TMA producer), target 48.
// Reset by the last exiting CTA (g_exit) -> graph-replay safe.
__device__ unsigned int g_rdy[KCHUNKS];
__device__ unsigned int g_exit;

#define SWZ(x) ((x) ^ (((x) >> 3) & 0x70))

__device__ __forceinline__ uint32_t h2u(__half2 h) {
    uint32_t u; memcpy(&u, &h, 4); return u;
}

__device__ __forceinline__ uint32_t smem_u32(const void* p) {
    uint32_t a;
    asm("{ .reg .u64 t; cvta.to.shared.u64 t, %1; cvt.u32.u64 %0, t; }"
        : "=r"(a) : "l"(p));
    return a;
}

// acquire-poll a global counter until it reaches tgt
__device__ __forceinline__ void wait_flag(const unsigned int* p, unsigned int tgt) {
    unsigned int v;
    while (true) {
        asm volatile("ld.acquire.gpu.global.b32 %0, [%1];"
                     : "=r"(v) : "l"(p) : "memory");
        if (v >= tgt) return;
        __nanosleep(64);
    }
}

// ---------------------------------------------------------------------------
// prep work units (identical math/layout to the proven R10 pre-pass kernels)
// ---------------------------------------------------------------------------
// A-block: cvt fp32->fp16 of inp rows [mt*128,+128), kvecs [c*8,+8)
__device__ __forceinline__ void prep_A(const float4* __restrict__ in,
                                       int mt, int c, int ptid, int nthr) {
    char* base = reinterpret_cast<char*>(g_A) + (size_t)(mt * 64 + c) * A_BYTES;
    for (int u = ptid; u < 1024; u += nthr) {
        int r = u >> 3, v = u & 7;
        int m = mt * 128 + r, kv = c * 8 + v;
        float4 v0 = in[(size_t)m * 1024 + kv * 2];
        float4 v1 = in[(size_t)m * 1024 + kv * 2 + 1];
        uint4 uu;
        uu.x = h2u(__floats2half2_rn(v0.x, v0.y));
        uu.y = h2u(__floats2half2_rn(v0.z, v0.w));
        uu.z = h2u(__floats2half2_rn(v1.x, v1.y));
        uu.w = h2u(__floats2half2_rn(v1.z, v1.w));
        *reinterpret_cast<uint4*>(base + SWZ((uint32_t)(r * 128 + v * 16))) = uu;
    }
}

// B-block: weight transform of rows [nt*256,+256), fin cols [c*64,+64)
__device__ __forceinline__ void prep_B(const float* __restrict__ W,
                                       const float* __restrict__ cw,
                                       const float* __restrict__ cb,
                                       const float* __restrict__ sk,
                                       int nt, int c, int ptid, int nthr) {
    int h = nt >> 2;                       // head constant within a 256-row block
    float kk[9];
#pragma unroll
    for (int j = 0; j < 9; ++j) kk[j] = cw[h * 9 + j];
    float bias = cb[h];
    float gate = 1.0f / (1.0f + expf(-sk[h]));
    const float* base = W + ((size_t)h << 10) * FIN;
    char* bbase = reinterpret_cast<char*>(g_B) + (size_t)(nt * 64 + c) * B_BYTES;

    for (int u = ptid; u < 2048; u += nthr) {
        int r = u >> 3, seg = u & 7;
        int rr0 = (nt & 3) * 256 + r;      // row within head
        int c0 = c * 64 + seg * 8;

        float acc[8], cen[8];
#pragma unroll
        for (int j = 0; j < 8; ++j) acc[j] = bias;
#pragma unroll
        for (int dr = -1; dr <= 1; ++dr) {
            int rr = rr0 + dr;
            if (rr < 0 || rr > 1023) continue;
            const float* rp = base + (size_t)rr * FIN;
            float x[10];
            x[0] = (c0 > 0) ? rp[c0 - 1] : 0.f;
            float4 a = *reinterpret_cast<const float4*>(rp + c0);
            float4 b = *reinterpret_cast<const float4*>(rp + c0 + 4);
            x[1] = a.x; x[2] = a.y; x[3] = a.z; x[4] = a.w;
            x[5] = b.x; x[6] = b.y; x[7] = b.z; x[8] = b.w;
            x[9] = (c0 + 8 < FIN) ? rp[c0 + 8] : 0.f;
            if (dr == 0) {
#pragma unroll
                for (int j = 0; j < 8; ++j) cen[j] = x[j + 1];
            }
            int kr = (dr + 1) * 3;
#pragma unroll
            for (int j = 0; j < 8; ++j)
                acc[j] += kk[kr] * x[j] + kk[kr + 1] * x[j + 1] + kk[kr + 2] * x[j + 2];
        }
        uint4 uu;
        uu.x = h2u(__floats2half2_rn(acc[0] + gate * cen[0], acc[1] + gate * cen[1]));
        uu.y = h2u(__floats2half2_rn(acc[2] + gate * cen[2], acc[3] + gate * cen[3]));
        uu.z = h2u(__floats2half2_rn(acc[4] + gate * cen[4], acc[5] + gate * cen[5]));
        uu.w = h2u(__floats2half2_rn(acc[6] + gate * cen[6], acc[7] + gate * cen[7]));
        *reinterpret_cast<uint4*>(bbase + SWZ((uint32_t)(r * 128 + seg * 16))) = uu;
    }
}

#if HAS_TCGEN05
__device__ __forceinline__ bool elect_one() {
    uint32_t pred;
    asm volatile(
        "{\n\t.reg .pred p;\n\t"
        "elect.sync _|p, 0xFFFFFFFF;\n\t"
        "selp.b32 %0, 1, 0, p;\n\t}"
        : "=r"(pred));
    return pred != 0;
}

// SW128 K-major smem descriptor: layout=SW128(2), version=1, SBO=64, LBO=1
static constexpr unsigned long long DESC_BASE =
    (2ULL << 61) | (1ULL << 46) | (64ULL << 32) | (1ULL << 16);

__device__ __forceinline__ uint64_t make_desc(uint32_t addr) {
    return DESC_BASE | ((uint64_t)(addr >> 4) & 0x3FFF);
}

__device__ __forceinline__ void wait_parity(uint32_t mbar, int phase) {
    asm volatile(
        "{\n\t.reg .pred P;\n\t"
        "WL%=:\n\t"
        "mbarrier.try_wait.parity.acquire.cta.shared::cta.b64 P, [%0], %1, 0x989680;\n\t"
        "@P bra.uni WD%=;\n\t"
        "bra.uni WL%=;\n\t"
        "WD%=:\n\t}"
        :: "r"(mbar), "r"((uint32_t)phase) : "memory");
}

__device__ __forceinline__ void bulk_g2s(uint32_t dst, const void* src,
                                         uint32_t bytes, uint32_t mbar) {
    asm volatile(
        "cp.async.bulk.shared::cluster.global.mbarrier::complete_tx::bytes "
        "[%0], [%1], %2, [%3];"
        :: "r"(dst), "l"(src), "r"(bytes), "r"(mbar) : "memory");
}

__device__ __forceinline__ void mma_f16_ss_cg2(uint32_t d_tmem, uint64_t a_desc,
                                               uint64_t b_desc, uint32_t en) {
    asm volatile(
        "{\n\t.reg .pred p;\n\t"
        "setp.ne.u32 p, %5, 0;\n\t"
        "tcgen05.mma.cta_group::2.kind::f16 [%0], %1, %2, %3, "
        "{%4, %4, %4, %4, %4, %4, %4, %4}, p;\n\t}"
        :: "r"(d_tmem), "l"(a_desc), "l"(b_desc), "r"(IDESC_CG2),
           "r"(0u), "r"(en)
        : "memory");
}

__device__ __forceinline__ void ldtm_x32(uint32_t* r, uint32_t tmem_addr) {
    asm volatile(
        "tcgen05.ld.sync.aligned.32x32b.x32.b32 "
        "{%0, %1, %2, %3, %4, %5, %6, %7, "
        " %8, %9, %10, %11, %12, %13, %14, %15, "
        " %16, %17, %18, %19, %20, %21, %22, %23, "
        " %24, %25, %26, %27, %28, %29, %30, %31}, [%32];"
        : "=r"(r[0]),  "=r"(r[1]),  "=r"(r[2]),  "=r"(r[3]),
          "=r"(r[4]),  "=r"(r[5]),  "=r"(r[6]),  "=r"(r[7]),
          "=r"(r[8]),  "=r"(r[9]),  "=r"(r[10]), "=r"(r[11]),
          "=r"(r[12]), "=r"(r[13]), "=r"(r[14]), "=r"(r[15]),
          "=r"(r[16]), "=r"(r[17]), "=r"(r[18]), "=r"(r[19]),
          "=r"(r[20]), "=r"(r[21]), "=r"(r[22]), "=r"(r[23]),
          "=r"(r[24]), "=r"(r[25]), "=r"(r[26]), "=r"(r[27]),
          "=r"(r[28]), "=r"(r[29]), "=r"(r[30]), "=r"(r[31])
        : "r"(tmem_addr));
}
#endif  // HAS_TCGEN05

// ---------------------------------------------------------------------------
// MEGAKERNEL: persistent cg2 tcgen05 GEMM with in-kernel prep.
//   warp 0: TMA producer (gated per chunk on g_rdy[k] >= 48)
//   warp 1: MMA issue (rank 0) / cross-CTA relay (rank 1)
//   warps 2-7: prep (3072 chunk-major items, grid-strided), then
//   warps 4-7: epilogue per tile (done/epifree barriers as R13)
// ---------------------------------------------------------------------------
__global__ void __launch_bounds__(256, 1) __cluster_dims__(2, 1, 1)
gemm_kernel(float* __restrict__ out, const float4* __restrict__ in,
            const float* __restrict__ W, const float* __restrict__ cw,
            const float* __restrict__ cb, const float* __restrict__ sk) {
    extern __shared__ char smem[];
    int tid = threadIdx.x;
    int p = blockIdx.x >> 1;         // pair id 0..73
    int rank = blockIdx.x & 1;       // cg2 pair rank
    int ntiles = (p < TWOTILE) ? 2 : 1;

#if HAS_TCGEN05
    uint32_t sb = smem_u32(smem);
    int wid = tid >> 5, lid = tid & 31;

    if (tid == 0) {
#pragma unroll
        for (int s = 0; s < NSTAGE; ++s) {
            asm volatile("mbarrier.init.shared.b64 [%0], %1;"
                         :: "r"(sb + SM_BAR + s * 16),
                            "r"(rank == 0 ? 2u : 1u) : "memory");
            asm volatile("mbarrier.init.shared.b64 [%0], 1;"
                         :: "r"(sb + SM_BAR + s * 16 + 8) : "memory");   // empty
        }
        asm volatile("mbarrier.init.shared.b64 [%0], 1;"
                     :: "r"(sb + SM_DONE) : "memory");
        asm volatile("mbarrier.init.shared.b64 [%0], 2;"
                     :: "r"(sb + SM_EPIFREE) : "memory");
    }
    if (wid == 0) {
        asm volatile("tcgen05.alloc.cta_group::2.sync.aligned.shared::cta.b32 [%0], 512;"
                     :: "r"(sb) : "memory");
        asm volatile("tcgen05.relinquish_alloc_permit.cta_group::2.sync.aligned;");
    }
    __syncthreads();
    asm volatile("barrier.cluster.arrive.aligned;" ::: "memory");
    asm volatile("barrier.cluster.wait.aligned;" ::: "memory");

    uint32_t tmem;
    asm volatile("ld.shared.b32 %0, [%1];" : "=r"(tmem) : "r"(sb));

    int total = ntiles * KCHUNKS;

    if (wid == 0) {
        if (elect_one()) {
            // ---- producer: flat chunk stream across tiles, flag-gated ----
            int eph[NSTAGE] = {0, 0, 0, 0};
            for (int c = 0; c < total; ++c) {
                int t = (c >= KCHUNKS) ? 1 : 0;
                int k = c & (KCHUNKS - 1);
                int s = c & (NSTAGE - 1);
                int tl = (t == 0) ? p : (p + NPAIRS);
                int pm = tl & 15, pn = tl >> 4;
                uint32_t full = sb + SM_BAR + s * 16;
                if (c >= NSTAGE) { wait_parity(full + 8, eph[s]); eph[s] ^= 1; }
                wait_flag(&g_rdy[k], RDY_TARGET);    // chunk prepped chip-wide?
                const char* gAp = reinterpret_cast<const char*>(g_A) +
                                  (size_t)(pm * 2 + rank) * 64 * A_BYTES;
                const char* gB0 = reinterpret_cast<const char*>(g_B) +
                                  (size_t)(pn * 2) * 64 * B_BYTES + (size_t)rank * BH_BYTES;
                const char* gB1 = reinterpret_cast<const char*>(g_B) +
                                  (size_t)(pn * 2 + 1) * 64 * B_BYTES + (size_t)rank * BH_BYTES;
                asm volatile("mbarrier.arrive.expect_tx.shared.b64 _, [%0], %1;"
                             :: "r"(full), "r"((uint32_t)TX_BYTES) : "memory");
                uint32_t dst = sb + SM_TILE0 + s * STAGE_BYTES;
                bulk_g2s(dst,             gAp + (size_t)k * A_BYTES, A_BYTES, full);
                bulk_g2s(dst + A_BYTES,   gB0 + (size_t)k * B_BYTES, BH_BYTES, full);
                bulk_g2s(dst + 2*A_BYTES, gB1 + (size_t)k * B_BYTES, BH_BYTES, full);
            }
        }
    } else if (wid == 1) {
        if (elect_one()) {
            if (rank == 0) {
                // ---- consumer (leader): 8 cg2 MMAs per chunk ----
                int fph[NSTAGE] = {0, 0, 0, 0};
                for (int c = 0; c < total; ++c) {
                    int k = c & (KCHUNKS - 1);
                    int s = c & (NSTAGE - 1);
                    uint32_t full = sb + SM_BAR + s * 16;
                    wait_parity(full, fph[s]); fph[s] ^= 1;
                    if (c == KCHUNKS) {
                        wait_parity(sb + SM_EPIFREE, 0);   // tile-1 TMEM drained
                        asm volatile("tcgen05.fence::after_thread_sync;" ::: "memory");
                    }
                    uint32_t sA = sb + SM_TILE0 + s * STAGE_BYTES;
                    uint64_t ad  = make_desc(sA);
                    uint64_t bd0 = make_desc(sA + A_BYTES);
                    uint64_t bd1 = make_desc(sA + 2 * A_BYTES);
#pragma unroll
                    for (int ks = 0; ks < 4; ++ks) {
                        uint32_t en = (uint32_t)(k | ks);   // tile-local reset
                        mma_f16_ss_cg2(tmem,       ad + ks * 2, bd0 + ks * 2, en);
                        mma_f16_ss_cg2(tmem + 256, ad + ks * 2, bd1 + ks * 2, en);
                    }
                    asm volatile(
                        "tcgen05.commit.cta_group::2.mbarrier::arrive::one."
                        "shared::cluster.multicast::cluster.b64 [%0], %1;"
                        :: "r"(full + 8), "h"((uint16_t)0x3) : "memory");
                    if (k == KCHUNKS - 1) {
                        asm volatile(
                            "tcgen05.commit.cta_group::2.mbarrier::arrive::one."
                            "shared::cluster.multicast::cluster.b64 [%0], %1;"
                            :: "r"(sb + SM_DONE), "h"((uint16_t)0x3) : "memory");
                    }
                }
            } else {
                // ---- relay (follower) ----
                int fph[NSTAGE] = {0, 0, 0, 0};
                for (int c = 0; c < total; ++c) {
                    int s = c & (NSTAGE - 1);
                    uint32_t full = sb + SM_BAR + s * 16;
                    wait_parity(full, fph[s]); fph[s] ^= 1;
                    asm volatile("mbarrier.arrive.shared::cluster.b64 _, [%0];"
                                 :: "r"(full & PEER_MASK) : "memory");
                }
            }
        }
    } else {
        // ---- warps 2..7: prep (192 threads), chunk-major, grid-strided ----
        int ptid = tid - 64;
        for (int it = blockIdx.x; it < PREP_ITEMS; it += GEMM_CTAS) {
            int c = it / ITEMS_PER_CHUNK;
            int j = it - c * ITEMS_PER_CHUNK;
            if (j < 32) prep_A(in, j, c, ptid, 192);
            else        prep_B(W, cw, cb, sk, j - 32, c, ptid, 192);
            __threadfence();
            asm volatile("bar.sync 3, 192;" ::: "memory");
            if (ptid == 0) atomicAdd(&g_rdy[c], 1u);
        }
        // ---- warps 4..7: epilogue, one per TMEM subpartition ----
        if (wid >= 4) {
            int sp = wid - 4;
            float* scr = reinterpret_cast<float*>(smem + SM_SCRATCH + sp * 4224);
            for (int t = 0; t < ntiles; ++t) {
                wait_parity(sb + SM_DONE, t);
                asm volatile("tcgen05.fence::after_thread_sync;" ::: "memory");
                int tl = (t == 0) ? p : (p + NPAIRS);
                int pm = tl & 15, pn = tl >> 4;
                int rowb = pm * 256 + rank * 128 + sp * 32;
                int colb = pn * 512;
#pragma unroll 1
                for (int cb = 0; cb < 16; ++cb) {
                    uint32_t regs[32];
                    ldtm_x32(regs, tmem + (uint32_t)(cb * 32) + ((uint32_t)sp << 21));
                    asm volatile("tcgen05.wait::ld.sync.aligned;" ::: "memory");
#pragma unroll
                    for (int q = 0; q < 32; ++q) scr[lid * 33 + q] = __uint_as_float(regs[q]);
                    __syncwarp();
#pragma unroll 4
                    for (int r2 = 0; r2 < 32; ++r2)
                        out[(size_t)(rowb + r2) * FOUT + colb + cb * 32 + lid] =
                            scr[r2 * 33 + lid];
                    __syncwarp();
                }
                if (t == 0 && ntiles == 2) {
                    asm volatile("tcgen05.fence::before_thread_sync;" ::: "memory");
                    asm volatile("bar.sync 2, 128;" ::: "memory");
                    if (sp == 0 && elect_one()) {
                        asm volatile("mbarrier.arrive.shared::cluster.b64 _, [%0];"
                                     :: "r"((sb + SM_EPIFREE) & PEER_MASK) : "memory");
                    }
                }
            }
            asm volatile("tcgen05.fence::before_thread_sync;" ::: "memory");
        }
    }

    __syncthreads();
    if (wid == 0) {
        asm volatile("tcgen05.dealloc.cta_group::2.sync.aligned.b32 %0, 512;" :: "r"(tmem));
    }
    asm volatile("barrier.cluster.arrive.aligned;" ::: "memory");
    asm volatile("barrier.cluster.wait.aligned;" ::: "memory");

    // last exiting CTA resets flags for the next graph replay
    if (tid == 0) {
        __threadfence();
        unsigned int old = atomicAdd(&g_exit, 1u);
        if (old == GEMM_CTAS - 1u) {
            for (int k = 0; k < KCHUNKS; ++k) g_rdy[k] = 0;
            __threadfence();
            atomicExch(&g_exit, 0u);
        }
    }

#else  // ---------- FFMA fallback (plain sm_103 pass; correctness safety net) ----
    // prep share first (all 256 threads), then flag-gated smem-tiled GEMM.
    for (int it = blockIdx.x; it < PREP_ITEMS; it += GEMM_CTAS) {
        int c = it / ITEMS_PER_CHUNK;
        int j = it - c * ITEMS_PER_CHUNK;
        if (j < 32) prep_A(in, j, c, tid, 256);
        else        prep_B(W, cw, cb, sk, j - 32, c, tid, 256);
        __threadfence();
        __syncthreads();
        if (tid == 0) atomicAdd(&g_rdy[c], 1u);
    }

    __half* tA = reinterpret_cast<__half*>(smem + SM_TILE0);            // 128x64
    __half* tB = reinterpret_cast<__half*>(smem + SM_TILE0 + 16384);    // 256x64
    int tm = tid >> 4, tn = tid & 15;

    const uint4* gA4 = reinterpret_cast<const uint4*>(g_A);
    const uint4* gB4 = reinterpret_cast<const uint4*>(g_B);

    for (int t = 0; t < ntiles; ++t) {
        int tl = (t == 0) ? p : (p + NPAIRS);
        int pm = tl & 15, pn = tl >> 4;
        int mt = pm * 2 + rank;
        int m0f = mt << 7;
        for (int qn = 0; qn < 2; ++qn) {
            int nt = pn * 2 + qn;
            int n0f = nt << 8;
            float acc[8][16];
#pragma unroll
            for (int r = 0; r < 8; ++r)
#pragma unroll
                for (int c2 = 0; c2 < 16; ++c2) acc[r][c2] = 0.f;

            for (int i = 0; i < KCHUNKS; ++i) {
                if (tid == 0) wait_flag(&g_rdy[i], RDY_TARGET);
                __syncthreads();
                uint32_t blkA = (uint32_t)mt * 64 + i;
                uint32_t blkB = (uint32_t)nt * 64 + i;
#pragma unroll
                for (int itr = 0; itr < 4; ++itr) {
                    int tt = tid + itr * 256;
                    int r = tt >> 3, v = tt & 7;
                    reinterpret_cast<uint4*>(tA)[r * 8 + v] =
                        gA4[(size_t)blkA * 1024 + (SWZ((uint32_t)(r * 128 + v * 16)) >> 4)];
                }
#pragma unroll
                for (int itr = 0; itr < 8; ++itr) {
                    int tt = tid + itr * 256;
                    int r = tt >> 3, v = tt & 7;
                    reinterpret_cast<uint4*>(tB)[r * 8 + v] =
                        gB4[(size_t)blkB * 2048 + (SWZ((uint32_t)(r * 128 + v * 16)) >> 4)];
                }
                __syncthreads();

                for (int k = 0; k < 64; ++k) {
                    float av[8], bv[16];
#pragma unroll
                    for (int r = 0; r < 8; ++r)
                        av[r] = __half2float(tA[(tm * 8 + r) * 64 + k]);
#pragma unroll
                    for (int c2 = 0; c2 < 16; ++c2)
                        bv[c2] = __half2float(tB[(tn * 16 + c2) * 64 + k]);
#pragma unroll
                    for (int r = 0; r < 8; ++r)
#pragma unroll
                        for (int c2 = 0; c2 < 16; ++c2) acc[r][c2] += av[r] * bv[c2];
                }
                __syncthreads();
            }
#pragma unroll
            for (int r = 0; r < 8; ++r)
#pragma unroll
                for (int c2 = 0; c2 < 16; ++c2)
                    out[(size_t)(m0f + tm * 8 + r) * FOUT + n0f + tn * 16 + c2] = acc[r][c2];
            __syncthreads();
        }
    }

    if (tid == 0) {
        __threadfence();
        unsigned int old = atomicAdd(&g_exit, 1u);
        if (old == GEMM_CTAS - 1u) {
            for (int k = 0; k < KCHUNKS; ++k) g_rdy[k] = 0;
            __threadfence();
            atomicExch(&g_exit, 0u);
        }
    }
#endif
}

// ---------------------------------------------------------------------------
extern "C" void kernel_launch(void* const* d_in, const int* in_sizes, int n_in,
                              void* d_out, int out_size) {
    const float* inp = (const float*)d_in[0];  // [2, 2048, 4096]
    const float* W   = (const float*)d_in[1];  // [4096, 4096]
    const float* cw  = (const float*)d_in[2];  // [4, 1, 3, 3]
    const float* cb  = (const float*)d_in[3];  // [4]
    const float* sk  = (const float*)d_in[4];  // [4, 1, 1]
    float* out = (float*)d_out;                // [2, 2048, 4096]

    cudaFuncSetAttribute(gemm_kernel,
                         cudaFuncAttributeMaxDynamicSharedMemorySize, SMEM_BYTES);

    gemm_kernel<<<GEMM_CTAS, 256, SMEM_BYTES>>>(
        out, (const float4*)inp, W, cw, cb, sk);
}

// round 15
// speedup vs baseline: 1.7607x; 1.7607x over previous
#include <cuda_runtime.h>
#include <cuda_fp16.h>
#include <cstdint>
#include <cstring>

// Problem dims
#define FIN   4096
#define FOUT  4096
#define MTOT  4096   // 2 * 2048

#define KCHUNKS 64          // K chunks of 64
#define NSTAGE  4
#define A_BYTES      16384  // 128 rows x 128B (this CTA's M-half)
#define BH_BYTES     16384  // one B half: 128 rows x 128B
#define B_BYTES      32768
#define STAGE_BYTES  49152  // A + B0half + B1half
#define TX_BYTES     49152  // per-CTA TMA bytes per stage

// Persistent schedule: 128 tiles (256M x 512N) over 74 cg2 pairs.
#define NPAIRS   74
#define NTILES   128
#define TWOTILE  (NTILES - NPAIRS)   // 54 pairs run 2 tiles

// SMEM layout (dynamic):
//   [0..4)      TMEM base ptr
//   [8..72)     full[s]=8+16s, empty[s]=16+16s  (s=0..3)
//   [72..80)    done mbarrier   (per-tile, parity 0 then 1)
//   [80..88)    epifree mbarrier (count 2, single use)
//   [1024 + s*49152)  stage s: A(16K) | B0half(16K) | B1half(16K)
//   [197632..214528)  epilogue scratch: 4 warps x 4224B
#define SM_BAR     8
#define SM_DONE    72
#define SM_EPIFREE 80
#define SM_TILE0   1024
#define SM_SCRATCH (1024 + NSTAGE * STAGE_BYTES)          // 197632
#define SMEM_BYTES (SM_SCRATCH + 4 * 4224)                // 214528, occ 1

// idesc kind::f16 cg2: dtype=F32(1<<4), a/b=F16(0), N=256 -> 32<<17, M=256 -> 16<<24
#define IDESC_CG2 0x10400010u
#define PEER_MASK 0xFEFFFFFFu

#if defined(__CUDA_ARCH__) && \
    (defined(__CUDA_ARCH_FEAT_SM103_ALL) || defined(__CUDA_ARCH_FEAT_SM100_ALL) || \
     defined(__CUDA_ARCH_FEAT_SM101_ALL))
#define HAS_TCGEN05 1
#else
#define HAS_TCGEN05 0
#endif

// fp16 staging in chunk-blocked, pre-SW128-swizzled layout:
// g_A: [mtile(32 x 128rows)][chunk(64)][16384B]
// g_B: [ntile(16 x 256rows)][chunk(64)][32768B]
__device__ __half g_A[(size_t)MTOT * FIN];
__device__ __half g_B[(size_t)FOUT * FIN];

#define SWZ(x) ((x) ^ (((x) >> 3) & 0x70))

__device__ __forceinline__ uint32_t h2u(__half2 h) {
    uint32_t u; memcpy(&u, &h, 4); return u;
}

__device__ __forceinline__ uint32_t smem_u32(const void* p) {
    uint32_t a;
    asm("{ .reg .u64 t; cvta.to.shared.u64 t, %1; cvt.u32.u64 %0, t; }"
        : "=r"(a) : "l"(p));
    return a;
}

#if HAS_TCGEN05
__device__ __forceinline__ bool elect_one() {
    uint32_t pred;
    asm volatile(
        "{\n\t.reg .pred p;\n\t"
        "elect.sync _|p, 0xFFFFFFFF;\n\t"
        "selp.b32 %0, 1, 0, p;\n\t}"
        : "=r"(pred));
    return pred != 0;
}

// SW128 K-major smem descriptor: layout=SW128(2), version=1, SBO=64, LBO=1
static constexpr unsigned long long DESC_BASE =
    (2ULL << 61) | (1ULL << 46) | (64ULL << 32) | (1ULL << 16);

__device__ __forceinline__ uint64_t make_desc(uint32_t addr) {
    return DESC_BASE | ((uint64_t)(addr >> 4) & 0x3FFF);
}

__device__ __forceinline__ void wait_parity(uint32_t mbar, int phase) {
    asm volatile(
        "{\n\t.reg .pred P;\n\t"
        "WL%=:\n\t"
        "mbarrier.try_wait.parity.acquire.cta.shared::cta.b64 P, [%0], %1, 0x989680;\n\t"
        "@P bra.uni WD%=;\n\t"
        "bra.uni WL%=;\n\t"
        "WD%=:\n\t}"
        :: "r"(mbar), "r"((uint32_t)phase) : "memory");
}

__device__ __forceinline__ void bulk_g2s(uint32_t dst, const void* src,
                                         uint32_t bytes, uint32_t mbar) {
    asm volatile(
        "cp.async.bulk.shared::cluster.global.mbarrier::complete_tx::bytes "
        "[%0], [%1], %2, [%3];"
        :: "r"(dst), "l"(src), "r"(bytes), "r"(mbar) : "memory");
}

__device__ __forceinline__ void mma_f16_ss_cg2(uint32_t d_tmem, uint64_t a_desc,
                                               uint64_t b_desc, uint32_t en) {
    asm volatile(
        "{\n\t.reg .pred p;\n\t"
        "setp.ne.u32 p, %5, 0;\n\t"
        "tcgen05.mma.cta_group::2.kind::f16 [%0], %1, %2, %3, "
        "{%4, %4, %4, %4, %4, %4, %4, %4}, p;\n\t}"
        :: "r"(d_tmem), "l"(a_desc), "l"(b_desc), "r"(IDESC_CG2),
           "r"(0u), "r"(en)
        : "memory");
}

__device__ __forceinline__ void ldtm_x32(uint32_t* r, uint32_t tmem_addr) {
    asm volatile(
        "tcgen05.ld.sync.aligned.32x32b.x32.b32 "
        "{%0, %1, %2, %3, %4, %5, %6, %7, "
        " %8, %9, %10, %11, %12, %13, %14, %15, "
        " %16, %17, %18, %19, %20, %21, %22, %23, "
        " %24, %25, %26, %27, %28, %29, %30, %31}, [%32];"
        : "=r"(r[0]),  "=r"(r[1]),  "=r"(r[2]),  "=r"(r[3]),
          "=r"(r[4]),  "=r"(r[5]),  "=r"(r[6]),  "=r"(r[7]),
          "=r"(r[8]),  "=r"(r[9]),  "=r"(r[10]), "=r"(r[11]),
          "=r"(r[12]), "=r"(r[13]), "=r"(r[14]), "=r"(r[15]),
          "=r"(r[16]), "=r"(r[17]), "=r"(r[18]), "=r"(r[19]),
          "=r"(r[20]), "=r"(r[21]), "=r"(r[22]), "=r"(r[23]),
          "=r"(r[24]), "=r"(r[25]), "=r"(r[26]), "=r"(r[27]),
          "=r"(r[28]), "=r"(r[29]), "=r"(r[30]), "=r"(r[31])
        : "r"(tmem_addr));
}
#endif  // HAS_TCGEN05

// ---------------------------------------------------------------------------
// Kernel 1: FUSED prep. Blocks [0,8192): fp32->fp16 cvt of inp -> g_A.
// Blocks [8192,16384): weight transform -> g_B (half a fout-row per block).
// Both parts are HBM-bound; fusing shares the bandwidth window and saves a
// launch gap vs the two-kernel R13 version.
// ---------------------------------------------------------------------------
__global__ void __launch_bounds__(256) prep_kernel(
    const float4* __restrict__ in, const float* __restrict__ W,
    const float* __restrict__ cw, const float* __restrict__ cb,
    const float* __restrict__ sk) {
    int tid = threadIdx.x;
    if (blockIdx.x < 8192) {
        // ---- cvt: one 16B output vector (8 k-values) per thread ----
        int i = blockIdx.x * 256 + tid;         // 0 .. 2M-1
        int m = i >> 9, kv = i & 511;
        float4 v0 = in[(size_t)m * 1024 + kv * 2];
        float4 v1 = in[(size_t)m * 1024 + kv * 2 + 1];
        uint4 u;
        u.x = h2u(__floats2half2_rn(v0.x, v0.y));
        u.y = h2u(__floats2half2_rn(v0.z, v0.w));
        u.z = h2u(__floats2half2_rn(v1.x, v1.y));
        u.w = h2u(__floats2half2_rn(v1.z, v1.w));
        uint32_t blk = (uint32_t)(m >> 7) * 64 + (kv >> 3);
        uint32_t off = SWZ((uint32_t)(m & 127) * 128 + (kv & 7) * 16);
        *reinterpret_cast<uint4*>(reinterpret_cast<char*>(g_A) +
                                  (size_t)blk * A_BYTES + off) = u;
    } else {
        // ---- xform: half a fout-row (2048 cols) per block, 8 cols/thread ----
        int j = blockIdx.x - 8192;
        int row = j >> 1;                       // fout index 0..4095
        int half = j & 1;
        int c0 = half * 2048 + tid * 8;
        int h = row >> 10, r = row & 1023;

        float kk[9];
#pragma unroll
        for (int t = 0; t < 9; ++t) kk[t] = cw[h * 9 + t];
        float bias = cb[h];
        float gate = 1.0f / (1.0f + expf(-sk[h]));

        float acc[8], cen[8];
#pragma unroll
        for (int t = 0; t < 8; ++t) acc[t] = bias;

        const float* base = W + (size_t)(h << 10) * FIN;
#pragma unroll
        for (int dr = -1; dr <= 1; ++dr) {
            int rr = r + dr;
            if (rr < 0 || rr > 1023) continue;
            const float* rp = base + (size_t)rr * FIN;
            float x[10];
            x[0] = (c0 > 0) ? rp[c0 - 1] : 0.f;
            float4 a = *reinterpret_cast<const float4*>(rp + c0);
            float4 b = *reinterpret_cast<const float4*>(rp + c0 + 4);
            x[1] = a.x; x[2] = a.y; x[3] = a.z; x[4] = a.w;
            x[5] = b.x; x[6] = b.y; x[7] = b.z; x[8] = b.w;
            x[9] = (c0 + 8 < FIN) ? rp[c0 + 8] : 0.f;
            if (dr == 0) {
#pragma unroll
                for (int t = 0; t < 8; ++t) cen[t] = x[t + 1];
            }
            int kr = (dr + 1) * 3;
#pragma unroll
            for (int t = 0; t < 8; ++t)
                acc[t] += kk[kr] * x[t] + kk[kr + 1] * x[t + 1] + kk[kr + 2] * x[t + 2];
        }

        uint4 u;
        u.x = h2u(__floats2half2_rn(acc[0] + gate * cen[0], acc[1] + gate * cen[1]));
        u.y = h2u(__floats2half2_rn(acc[2] + gate * cen[2], acc[3] + gate * cen[3]));
        u.z = h2u(__floats2half2_rn(acc[4] + gate * cen[4], acc[5] + gate * cen[5]));
        u.w = h2u(__floats2half2_rn(acc[6] + gate * cen[6], acc[7] + gate * cen[7]));
        int kv = half * 256 + tid;              // 16B-vector index in the row
        uint32_t blk = (uint32_t)(row >> 8) * 64 + (kv >> 3);
        uint32_t off = SWZ((uint32_t)(row & 255) * 128 + (kv & 7) * 16);
        *reinterpret_cast<uint4*>(reinterpret_cast<char*>(g_B) +
                                  (size_t)blk * B_BYTES + off) = u;
    }
}

// ---------------------------------------------------------------------------
// Kernel 2: PERSISTENT cg2 tcgen05 GEMM (R13 structure, unchanged).
// 74 pairs, each 1-2 tiles of 256(M) x 512(N); one TMEM alloc + one pipeline
// fill per pair; epilogue on warps 4-7 with done/epifree barriers.
// ---------------------------------------------------------------------------
__global__ void __launch_bounds__(256, 1) __cluster_dims__(2, 1, 1)
gemm_kernel(float* __restrict__ out) {
    extern __shared__ char smem[];
    int tid = threadIdx.x;
    int p = blockIdx.x >> 1;         // pair id 0..73
    int rank = blockIdx.x & 1;       // cg2 pair rank
    int ntiles = (p < TWOTILE) ? 2 : 1;

#if HAS_TCGEN05
    uint32_t sb = smem_u32(smem);
    int wid = tid >> 5, lid = tid & 31;

    if (tid == 0) {
#pragma unroll
        for (int s = 0; s < NSTAGE; ++s) {
            asm volatile("mbarrier.init.shared.b64 [%0], %1;"
                         :: "r"(sb + SM_BAR + s * 16),
                            "r"(rank == 0 ? 2u : 1u) : "memory");
            asm volatile("mbarrier.init.shared.b64 [%0], 1;"
                         :: "r"(sb + SM_BAR + s * 16 + 8) : "memory");   // empty
        }
        asm volatile("mbarrier.init.shared.b64 [%0], 1;"
                     :: "r"(sb + SM_DONE) : "memory");
        asm volatile("mbarrier.init.shared.b64 [%0], 2;"
                     :: "r"(sb + SM_EPIFREE) : "memory");
    }
    if (wid == 0) {
        asm volatile("tcgen05.alloc.cta_group::2.sync.aligned.shared::cta.b32 [%0], 512;"
                     :: "r"(sb) : "memory");
        asm volatile("tcgen05.relinquish_alloc_permit.cta_group::2.sync.aligned;");
    }
    __syncthreads();
    asm volatile("barrier.cluster.arrive.aligned;" ::: "memory");
    asm volatile("barrier.cluster.wait.aligned;" ::: "memory");

    uint32_t tmem;
    asm volatile("ld.shared.b32 %0, [%1];" : "=r"(tmem) : "r"(sb));

    int total = ntiles * KCHUNKS;

    if (wid == 0 && elect_one()) {
        // ---- producer: flat chunk stream across tiles ----
        int eph[NSTAGE] = {0, 0, 0, 0};
        for (int c = 0; c < total; ++c) {
            int t = (c >= KCHUNKS) ? 1 : 0;
            int k = c & (KCHUNKS - 1);
            int s = c & (NSTAGE - 1);
            int tl = (t == 0) ? p : (p + NPAIRS);
            int pm = tl & 15, pn = tl >> 4;
            uint32_t full = sb + SM_BAR + s * 16;
            if (c >= NSTAGE) { wait_parity(full + 8, eph[s]); eph[s] ^= 1; }
            const char* gAp = reinterpret_cast<const char*>(g_A) +
                              (size_t)(pm * 2 + rank) * 64 * A_BYTES;
            const char* gB0 = reinterpret_cast<const char*>(g_B) +
                              (size_t)(pn * 2) * 64 * B_BYTES + (size_t)rank * BH_BYTES;
            const char* gB1 = reinterpret_cast<const char*>(g_B) +
                              (size_t)(pn * 2 + 1) * 64 * B_BYTES + (size_t)rank * BH_BYTES;
            asm volatile("mbarrier.arrive.expect_tx.shared.b64 _, [%0], %1;"
                         :: "r"(full), "r"((uint32_t)TX_BYTES) : "memory");
            uint32_t dst = sb + SM_TILE0 + s * STAGE_BYTES;
            bulk_g2s(dst,             gAp + (size_t)k * A_BYTES, A_BYTES, full);
            bulk_g2s(dst + A_BYTES,   gB0 + (size_t)k * B_BYTES, BH_BYTES, full);
            bulk_g2s(dst + 2*A_BYTES, gB1 + (size_t)k * B_BYTES, BH_BYTES, full);
        }
    } else if (wid == 1 && elect_one()) {
        if (rank == 0) {
            // ---- consumer (leader): 8 cg2 MMAs per chunk ----
            int fph[NSTAGE] = {0, 0, 0, 0};
            for (int c = 0; c < total; ++c) {
                int k = c & (KCHUNKS - 1);
                int s = c & (NSTAGE - 1);
                uint32_t full = sb + SM_BAR + s * 16;
                wait_parity(full, fph[s]); fph[s] ^= 1;
                if (c == KCHUNKS) {
                    wait_parity(sb + SM_EPIFREE, 0);   // tile-1 TMEM drained
                    asm volatile("tcgen05.fence::after_thread_sync;" ::: "memory");
                }
                uint32_t sA = sb + SM_TILE0 + s * STAGE_BYTES;
                uint64_t ad  = make_desc(sA);
                uint64_t bd0 = make_desc(sA + A_BYTES);
                uint64_t bd1 = make_desc(sA + 2 * A_BYTES);
#pragma unroll
                for (int ks = 0; ks < 4; ++ks) {   // K=16 steps; +32B per step
                    uint32_t en = (uint32_t)(k | ks);   // tile-local reset
                    mma_f16_ss_cg2(tmem,       ad + ks * 2, bd0 + ks * 2, en);
                    mma_f16_ss_cg2(tmem + 256, ad + ks * 2, bd1 + ks * 2, en);
                }
                asm volatile(
                    "tcgen05.commit.cta_group::2.mbarrier::arrive::one."
                    "shared::cluster.multicast::cluster.b64 [%0], %1;"
                    :: "r"(full + 8), "h"((uint16_t)0x3) : "memory");
                if (k == KCHUNKS - 1) {
                    asm volatile(
                        "tcgen05.commit.cta_group::2.mbarrier::arrive::one."
                        "shared::cluster.multicast::cluster.b64 [%0], %1;"
                        :: "r"(sb + SM_DONE), "h"((uint16_t)0x3) : "memory");
                }
            }
        } else {
            // ---- relay (follower): own data ready -> arrive leader's full ----
            int fph[NSTAGE] = {0, 0, 0, 0};
            for (int c = 0; c < total; ++c) {
                int s = c & (NSTAGE - 1);
                uint32_t full = sb + SM_BAR + s * 16;
                wait_parity(full, fph[s]); fph[s] ^= 1;
                asm volatile("mbarrier.arrive.shared::cluster.b64 _, [%0];"
                             :: "r"(full & PEER_MASK) : "memory");
            }
        }
    }

    // ---- epilogue warps 4..7: one per TMEM subpartition ----
    if (wid >= 4) {
        int sp = wid - 4;
        float* scr = reinterpret_cast<float*>(smem + SM_SCRATCH + sp * 4224);
        for (int t = 0; t < ntiles; ++t) {
            wait_parity(sb + SM_DONE, t);
            asm volatile("tcgen05.fence::after_thread_sync;" ::: "memory");
            int tl = (t == 0) ? p : (p + NPAIRS);
            int pm = tl & 15, pn = tl >> 4;
            int rowb = pm * 256 + rank * 128 + sp * 32;
            int colb = pn * 512;
#pragma unroll 1
            for (int cb = 0; cb < 16; ++cb) {
                uint32_t regs[32];
                ldtm_x32(regs, tmem + (uint32_t)(cb * 32) + ((uint32_t)sp << 21));
                asm volatile("tcgen05.wait::ld.sync.aligned;" ::: "memory");
#pragma unroll
                for (int q = 0; q < 32; ++q) scr[lid * 33 + q] = __uint_as_float(regs[q]);
                __syncwarp();
#pragma unroll 4
                for (int r2 = 0; r2 < 32; ++r2)
                    out[(size_t)(rowb + r2) * FOUT + colb + cb * 32 + lid] =
                        scr[r2 * 33 + lid];
                __syncwarp();
            }
            if (t == 0 && ntiles == 2) {
                asm volatile("tcgen05.fence::before_thread_sync;" ::: "memory");
                asm volatile("bar.sync 2, 128;" ::: "memory");
                if (sp == 0 && elect_one()) {
                    asm volatile("mbarrier.arrive.shared::cluster.b64 _, [%0];"
                                 :: "r"((sb + SM_EPIFREE) & PEER_MASK) : "memory");
                }
            }
        }
        asm volatile("tcgen05.fence::before_thread_sync;" ::: "memory");
    }

    __syncthreads();
    if (wid == 0) {
        asm volatile("tcgen05.dealloc.cta_group::2.sync.aligned.b32 %0, 512;" :: "r"(tmem));
    }
    asm volatile("barrier.cluster.arrive.aligned;" ::: "memory");
    asm volatile("barrier.cluster.wait.aligned;" ::: "memory");

#else  // ---------- FFMA fallback (plain sm_103 pass; correctness safety net) ----
    __half* tA = reinterpret_cast<__half*>(smem + SM_TILE0);            // 128x64
    __half* tB = reinterpret_cast<__half*>(smem + SM_TILE0 + 16384);    // 256x64
    int tm = tid >> 4, tn = tid & 15;

    const uint4* gA4 = reinterpret_cast<const uint4*>(g_A);
    const uint4* gB4 = reinterpret_cast<const uint4*>(g_B);

    for (int t = 0; t < ntiles; ++t) {
        int tl = (t == 0) ? p : (p + NPAIRS);
        int pm = tl & 15, pn = tl >> 4;
        int mt = pm * 2 + rank;
        int m0f = mt << 7;
        for (int qn = 0; qn < 2; ++qn) {
            int nt = pn * 2 + qn;
            int n0f = nt << 8;
            float acc[8][16];
#pragma unroll
            for (int r = 0; r < 8; ++r)
#pragma unroll
                for (int c = 0; c < 16; ++c) acc[r][c] = 0.f;

            for (int i = 0; i < KCHUNKS; ++i) {
                __syncthreads();
                uint32_t blkA = (uint32_t)mt * 64 + i;
                uint32_t blkB = (uint32_t)nt * 64 + i;
#pragma unroll
                for (int it = 0; it < 4; ++it) {
                    int tt = tid + it * 256;
                    int r = tt >> 3, v = tt & 7;
                    reinterpret_cast<uint4*>(tA)[r * 8 + v] =
                        gA4[(size_t)blkA * 1024 + (SWZ((uint32_t)(r * 128 + v * 16)) >> 4)];
                }
#pragma unroll
                for (int it = 0; it < 8; ++it) {
                    int tt = tid + it * 256;
                    int r = tt >> 3, v = tt & 7;
                    reinterpret_cast<uint4*>(tB)[r * 8 + v] =
                        gB4[(size_t)blkB * 2048 + (SWZ((uint32_t)(r * 128 + v * 16)) >> 4)];
                }
                __syncthreads();

                for (int k = 0; k < 64; ++k) {
                    float av[8], bv[16];
#pragma unroll
                    for (int r = 0; r < 8; ++r)
                        av[r] = __half2float(tA[(tm * 8 + r) * 64 + k]);
#pragma unroll
                    for (int c = 0; c < 16; ++c)
                        bv[c] = __half2float(tB[(tn * 16 + c) * 64 + k]);
#pragma unroll
                    for (int r = 0; r < 8; ++r)
#pragma unroll
                        for (int c = 0; c < 16; ++c) acc[r][c] += av[r] * bv[c];
                }
                __syncthreads();
            }
#pragma unroll
            for (int r = 0; r < 8; ++r)
#pragma unroll
                for (int c = 0; c < 16; ++c)
                    out[(size_t)(m0f + tm * 8 + r) * FOUT + n0f + tn * 16 + c] = acc[r][c];
            __syncthreads();
        }
    }
#endif
}

// ---------------------------------------------------------------------------
extern "C" void kernel_launch(void* const* d_in, const int* in_sizes, int n_in,
                              void* d_out, int out_size) {
    const float* inp = (const float*)d_in[0];  // [2, 2048, 4096]
    const float* W   = (const float*)d_in[1];  // [4096, 4096]
    const float* cw  = (const float*)d_in[2];  // [4, 1, 3, 3]
    const float* cb  = (const float*)d_in[3];  // [4]
    const float* sk  = (const float*)d_in[4];  // [4, 1, 1]
    float* out = (float*)d_out;                // [2, 2048, 4096]

    cudaFuncSetAttribute(gemm_kernel,
                         cudaFuncAttributeMaxDynamicSharedMemorySize, SMEM_BYTES);

    prep_kernel<<<16384, 256>>>((const float4*)inp, W, cw, cb, sk);
    gemm_kernel<<<dim3(2 * NPAIRS, 1), 256, SMEM_BYTES>>>(out);
}